// round 5
// baseline (speedup 1.0000x reference)
#include <cuda_runtime.h>
#include <cuda_bf16.h>
#include <cstdint>
#include <math.h>

#define Bq 4
#define Nq 2048
#define Dq 1024
#define MTOT (Bq * Nq)   // 8192

typedef __nv_bfloat16 bf16;

// ---------------- scratch (device globals; allocation-free) ----------------
__device__ __align__(16) bf16  g_xb [(size_t)MTOT * Dq];
__device__ __align__(16) bf16  g_Wqb[(size_t)Dq * Dq];
__device__ __align__(16) bf16  g_Wkb[(size_t)Dq * Dq];
__device__ __align__(16) bf16  g_Wvb[(size_t)Dq * Dq];
__device__ __align__(16) bf16  g_Qb [(size_t)MTOT * Dq];
__device__ __align__(16) bf16  g_Kb [(size_t)MTOT * Dq];
__device__ __align__(16) bf16  g_Vt [(size_t)Bq * Dq * Nq];   // [b][d][n]
__device__ __align__(16) float g_S  [(size_t)Bq * Nq * Nq];
__device__ __align__(16) bf16  g_Pb [(size_t)Bq * Nq * Nq];

// ---------------- helpers ----------------
__device__ __forceinline__ uint32_t smem_u32(const void* p) {
    uint32_t a;
    asm("{ .reg .u64 t; cvta.to.shared.u64 t, %1; cvt.u32.u64 %0, t; }" : "=r"(a) : "l"(p));
    return a;
}
#define CP_ASYNC16(dst, src) asm volatile("cp.async.cg.shared.global [%0], [%1], 16;" :: "r"(dst), "l"(src))
#define CP_COMMIT()          asm volatile("cp.async.commit_group;" ::: "memory")
#define CP_WAIT1()           asm volatile("cp.async.wait_group 1;" ::: "memory")

#define LDSM4(r0, r1, r2, r3, addr)                                             \
    asm volatile("ldmatrix.sync.aligned.m8n8.x4.shared.b16 {%0,%1,%2,%3}, [%4];" \
        : "=r"(r0), "=r"(r1), "=r"(r2), "=r"(r3) : "r"(addr))

#define MMA16816(d, a, b0, b1)                                                  \
    asm volatile("mma.sync.aligned.m16n8k16.row.col.f32.bf16.bf16.f32 "         \
        "{%0,%1,%2,%3}, {%4,%5,%6,%7}, {%8,%9}, {%0,%1,%2,%3};"                 \
        : "+f"((d)[0]), "+f"((d)[1]), "+f"((d)[2]), "+f"((d)[3])                \
        : "r"((a)[0]), "r"((a)[1]), "r"((a)[2]), "r"((a)[3]), "r"(b0), "r"(b1))

// ---------------------------------------------------------------------------
// NT bf16 HMMA GEMM: C[m,n] = sum_k A[m,k]*B[n,k]. Tile 128x128, BK=64,
// 3-stage cp.async pipeline, 4 warps (2x2), warp tile 64x64, fp32 accum.
// Smem row = 128B, chunk swizzle (ch ^ (r&7)) -> conflict-free ldmatrix.
// EPI 0: +bias -> bf16 C           EPI 3: +bias -> bf16 transposed (Vt)
// EPI 1: *1/32 -> fp32 S           EPI 2: *gamma + x -> fp32 out
// ---------------------------------------------------------------------------
#define BKq 64
#define STAGE_BYTES 32768u   // A tile 16KB + B tile 16KB

template <int EPI>
__global__ __launch_bounds__(128, 2)
void hgemm(const bf16* __restrict__ A, const bf16* __restrict__ Bm,
           int lda, int ldb, int K, long long sA, long long sB, long long sC,
           int ldc, const float* __restrict__ ep0, const float* __restrict__ ep1,
           void* __restrict__ Cout)
{
    extern __shared__ char smem[];
    const int tid  = threadIdx.x;
    const int wid  = tid >> 5;
    const int lane = tid & 31;
    const int wm   = wid & 1;    // 2 warps along M (64 rows each)
    const int wn   = wid >> 1;   // 2 warps along N (64 cols each)
    const int z    = blockIdx.z;
    const int rowBase = blockIdx.y * 128;
    const int colBase = blockIdx.x * 128;

    const bf16* Ab = A + (long long)z * sA;
    const bf16* Bb = Bm + (long long)z * sB;
    const uint32_t sbase = smem_u32(smem);

    const int niter = K / BKq;

    // stage loader: 128 rows x 8 chunks(16B) per operand, 128 threads
#define ISSUE_STAGE(c, s) do {                                                  \
        uint32_t aOff = sbase + (uint32_t)(s) * STAGE_BYTES;                    \
        uint32_t bOff = aOff + 16384u;                                          \
        _Pragma("unroll")                                                       \
        for (int i = 0; i < 8; i++) {                                           \
            int idx = tid + i * 128;                                            \
            int r = idx >> 3, ch = idx & 7;                                     \
            uint32_t sw = (uint32_t)((ch ^ (r & 7)) << 4) + (uint32_t)r * 128u; \
            CP_ASYNC16(aOff + sw, Ab + (size_t)(rowBase + r) * lda + (c) * BKq + ch * 8); \
            CP_ASYNC16(bOff + sw, Bb + (size_t)(colBase + r) * ldb + (c) * BKq + ch * 8); \
        }                                                                       \
        CP_COMMIT();                                                            \
    } while (0)

    float acc[4][8][4];
#pragma unroll
    for (int i = 0; i < 4; i++)
#pragma unroll
        for (int j = 0; j < 8; j++)
#pragma unroll
            for (int e = 0; e < 4; e++) acc[i][j][e] = 0.f;

    ISSUE_STAGE(0, 0);
    ISSUE_STAGE(1, 1);

    for (int c = 0; c < niter; c++) {
        CP_WAIT1();
        __syncthreads();
        if (c + 2 < niter) { ISSUE_STAGE(c + 2, (c + 2) % 3); }
        else               { CP_COMMIT(); }   // keep group count uniform

        uint32_t aBase = sbase + (uint32_t)(c % 3) * STAGE_BYTES;
        uint32_t bBase = aBase + 16384u;

#pragma unroll
        for (int kk = 0; kk < 4; kk++) {
            const int ch = kk * 2 + (lane >> 4);
            uint32_t af[4][4];
#pragma unroll
            for (int i = 0; i < 4; i++) {
                int r = wm * 64 + i * 16 + (lane & 15);
                uint32_t addr = aBase + (uint32_t)r * 128u + (uint32_t)((ch ^ (r & 7)) << 4);
                LDSM4(af[i][0], af[i][1], af[i][2], af[i][3], addr);
            }
            uint32_t bfr[4][4];
#pragma unroll
            for (int jj = 0; jj < 4; jj++) {
                int r = wn * 64 + jj * 16 + (lane & 15);
                uint32_t addr = bBase + (uint32_t)r * 128u + (uint32_t)((ch ^ (r & 7)) << 4);
                LDSM4(bfr[jj][0], bfr[jj][1], bfr[jj][2], bfr[jj][3], addr);
            }
#pragma unroll
            for (int i = 0; i < 4; i++)
#pragma unroll
                for (int j = 0; j < 8; j++)
                    MMA16816(acc[i][j], af[i], bfr[j >> 1][j & 1], bfr[j >> 1][(j & 1) + 2]);
        }
    }
#undef ISSUE_STAGE

    // ---------------- epilogue ----------------
    const float gma = (EPI == 2) ? ep1[0] : 0.f;

#pragma unroll
    for (int i = 0; i < 4; i++) {
#pragma unroll
        for (int j = 0; j < 8; j++) {
            const int row0 = rowBase + wm * 64 + i * 16 + (lane >> 2);
            const int row1 = row0 + 8;
            const int col  = colBase + wn * 64 + j * 8 + (lane & 3) * 2;
            const float a0 = acc[i][j][0], a1 = acc[i][j][1];
            const float a2 = acc[i][j][2], a3 = acc[i][j][3];

            if (EPI == 0) {
                bf16* C = (bf16*)Cout;
                float b0 = ep0[col], b1 = ep0[col + 1];
                __nv_bfloat162 h0 = __floats2bfloat162_rn(a0 + b0, a1 + b1);
                __nv_bfloat162 h1 = __floats2bfloat162_rn(a2 + b0, a3 + b1);
                *(__nv_bfloat162*)(C + (size_t)row0 * ldc + col) = h0;
                *(__nv_bfloat162*)(C + (size_t)row1 * ldc + col) = h1;
            } else if (EPI == 3) {
                bf16* Vt = (bf16*)Cout;
                float b0 = ep0[col], b1 = ep0[col + 1];
                int bz  = row0 >> 11;           // tile never crosses batch boundary
                int mm0 = row0 & 2047, mm1 = row1 & 2047;
                size_t base0 = ((size_t)(bz << 10) + col) * Nq;
                size_t base1 = ((size_t)(bz << 10) + col + 1) * Nq;
                Vt[base0 + mm0] = __float2bfloat16(a0 + b0);
                Vt[base1 + mm0] = __float2bfloat16(a1 + b1);
                Vt[base0 + mm1] = __float2bfloat16(a2 + b0);
                Vt[base1 + mm1] = __float2bfloat16(a3 + b1);
            } else if (EPI == 1) {
                float* S = (float*)Cout + (long long)z * sC;
                float2 v0 = make_float2(a0 * 0.03125f, a1 * 0.03125f);
                float2 v1 = make_float2(a2 * 0.03125f, a3 * 0.03125f);
                *(float2*)(S + (size_t)row0 * ldc + col) = v0;
                *(float2*)(S + (size_t)row1 * ldc + col) = v1;
            } else {
                float* O = (float*)Cout + (long long)z * sC;
                const float* xp = ep0 + (long long)z * sC;
                float2 x0 = *(const float2*)(xp + (size_t)row0 * ldc + col);
                float2 x1 = *(const float2*)(xp + (size_t)row1 * ldc + col);
                float2 v0 = make_float2(a0 * gma + x0.x, a1 * gma + x0.y);
                float2 v1 = make_float2(a2 * gma + x1.x, a3 * gma + x1.y);
                *(float2*)(O + (size_t)row0 * ldc + col) = v0;
                *(float2*)(O + (size_t)row1 * ldc + col) = v1;
            }
        }
    }
}

// ---------------------------------------------------------------------------
__global__ __launch_bounds__(256)
void cvt_f32_bf16(const float* __restrict__ in, bf16* __restrict__ out, int n4)
{
    int i = blockIdx.x * blockDim.x + threadIdx.x;
    if (i < n4) {
        float4 v = reinterpret_cast<const float4*>(in)[i];
        __nv_bfloat162 a = __floats2bfloat162_rn(v.x, v.y);
        __nv_bfloat162 b = __floats2bfloat162_rn(v.z, v.w);
        uint2 u;
        u.x = *(uint32_t*)&a;
        u.y = *(uint32_t*)&b;
        reinterpret_cast<uint2*>(out)[i] = u;
    }
}

// Row softmax over 2048 fp32 scores -> bf16 probabilities
__global__ __launch_bounds__(256)
void softmax2048(const float* __restrict__ S, bf16* __restrict__ P)
{
    const int row = blockIdx.x;
    const float* p = S + (size_t)row * Nq;
    bf16* po = P + (size_t)row * Nq;
    const int tid = threadIdx.x;

    float4 v0 = *reinterpret_cast<const float4*>(&p[tid * 4]);
    float4 v1 = *reinterpret_cast<const float4*>(&p[tid * 4 + 1024]);

    __shared__ float red[8];

    float m = fmaxf(fmaxf(fmaxf(v0.x, v0.y), fmaxf(v0.z, v0.w)),
                    fmaxf(fmaxf(v1.x, v1.y), fmaxf(v1.z, v1.w)));
#pragma unroll
    for (int o = 16; o > 0; o >>= 1) m = fmaxf(m, __shfl_xor_sync(0xFFFFFFFFu, m, o));
    if ((tid & 31) == 0) red[tid >> 5] = m;
    __syncthreads();
    if (tid < 32) {
        float t = (tid < 8) ? red[tid] : -INFINITY;
#pragma unroll
        for (int o = 4; o > 0; o >>= 1) t = fmaxf(t, __shfl_xor_sync(0xFFFFFFFFu, t, o));
        if (tid == 0) red[0] = t;
    }
    __syncthreads();
    m = red[0];
    __syncthreads();

    v0.x = __expf(v0.x - m); v0.y = __expf(v0.y - m);
    v0.z = __expf(v0.z - m); v0.w = __expf(v0.w - m);
    v1.x = __expf(v1.x - m); v1.y = __expf(v1.y - m);
    v1.z = __expf(v1.z - m); v1.w = __expf(v1.w - m);
    float s = v0.x + v0.y + v0.z + v0.w + v1.x + v1.y + v1.z + v1.w;
#pragma unroll
    for (int o = 16; o > 0; o >>= 1) s += __shfl_xor_sync(0xFFFFFFFFu, s, o);
    if ((tid & 31) == 0) red[tid >> 5] = s;
    __syncthreads();
    if (tid < 32) {
        float t = (tid < 8) ? red[tid] : 0.f;
#pragma unroll
        for (int o = 4; o > 0; o >>= 1) t += __shfl_xor_sync(0xFFFFFFFFu, t, o);
        if (tid == 0) red[0] = t;
    }
    __syncthreads();
    float inv = 1.f / red[0];

    v0.x *= inv; v0.y *= inv; v0.z *= inv; v0.w *= inv;
    v1.x *= inv; v1.y *= inv; v1.z *= inv; v1.w *= inv;

    __nv_bfloat162 h0 = __floats2bfloat162_rn(v0.x, v0.y);
    __nv_bfloat162 h1 = __floats2bfloat162_rn(v0.z, v0.w);
    __nv_bfloat162 h2 = __floats2bfloat162_rn(v1.x, v1.y);
    __nv_bfloat162 h3 = __floats2bfloat162_rn(v1.z, v1.w);
    uint2 u0, u1;
    u0.x = *(uint32_t*)&h0; u0.y = *(uint32_t*)&h1;
    u1.x = *(uint32_t*)&h2; u1.y = *(uint32_t*)&h3;
    *reinterpret_cast<uint2*>(po + tid * 4)        = u0;
    *reinterpret_cast<uint2*>(po + tid * 4 + 1024) = u1;
}

// ---------------------------------------------------------------------------
extern "C" void kernel_launch(void* const* d_in, const int* in_sizes, int n_in,
                              void* d_out, int out_size)
{
    const float* x     = (const float*)d_in[0];
    const float* Wq    = (const float*)d_in[1];
    const float* bqv   = (const float*)d_in[2];
    const float* Wk    = (const float*)d_in[3];
    const float* bkv   = (const float*)d_in[4];
    const float* Wv    = (const float*)d_in[5];
    const float* bvv   = (const float*)d_in[6];
    const float* gamma = (const float*)d_in[7];
    float* out = (float*)d_out;

    bf16 *xb, *Wqb, *Wkb, *Wvb, *Qb, *Kb, *Vt, *Pb;
    float* Sp;
    cudaGetSymbolAddress((void**)&xb,  g_xb);
    cudaGetSymbolAddress((void**)&Wqb, g_Wqb);
    cudaGetSymbolAddress((void**)&Wkb, g_Wkb);
    cudaGetSymbolAddress((void**)&Wvb, g_Wvb);
    cudaGetSymbolAddress((void**)&Qb,  g_Qb);
    cudaGetSymbolAddress((void**)&Kb,  g_Kb);
    cudaGetSymbolAddress((void**)&Vt,  g_Vt);
    cudaGetSymbolAddress((void**)&Sp,  g_S);
    cudaGetSymbolAddress((void**)&Pb,  g_Pb);

    const int SMEM = 96 * 1024;
    cudaFuncSetAttribute(hgemm<0>, cudaFuncAttributeMaxDynamicSharedMemorySize, SMEM);
    cudaFuncSetAttribute(hgemm<1>, cudaFuncAttributeMaxDynamicSharedMemorySize, SMEM);
    cudaFuncSetAttribute(hgemm<2>, cudaFuncAttributeMaxDynamicSharedMemorySize, SMEM);
    cudaFuncSetAttribute(hgemm<3>, cudaFuncAttributeMaxDynamicSharedMemorySize, SMEM);

    // fp32 -> bf16 conversions
    cvt_f32_bf16<<<(MTOT * Dq / 4 + 255) / 256, 256>>>(x, xb, MTOT * Dq / 4);
    cvt_f32_bf16<<<(Dq * Dq / 4 + 255) / 256, 256>>>(Wq, Wqb, Dq * Dq / 4);
    cvt_f32_bf16<<<(Dq * Dq / 4 + 255) / 256, 256>>>(Wk, Wkb, Dq * Dq / 4);
    cvt_f32_bf16<<<(Dq * Dq / 4 + 255) / 256, 256>>>(Wv, Wvb, Dq * Dq / 4);

    dim3 blk(128);

    // projections: M=8192, N=1024, K=1024
    dim3 gP(Dq / 128, MTOT / 128, 1);
    hgemm<0><<<gP, blk, SMEM>>>(xb, Wqb, Dq, Dq, Dq, 0, 0, 0, Dq, bqv, nullptr, Qb);
    hgemm<0><<<gP, blk, SMEM>>>(xb, Wkb, Dq, Dq, Dq, 0, 0, 0, Dq, bkv, nullptr, Kb);
    hgemm<3><<<gP, blk, SMEM>>>(xb, Wvb, Dq, Dq, Dq, 0, 0, 0, Dq, bvv, nullptr, Vt);

    // scores = Q K^T / 32 (fp32), per batch
    dim3 gS(Nq / 128, Nq / 128, Bq);
    hgemm<1><<<gS, blk, SMEM>>>(Qb, Kb, Dq, Dq, Dq,
                                (long long)Nq * Dq, (long long)Nq * Dq,
                                (long long)Nq * Nq, Nq, nullptr, nullptr, Sp);

    // softmax -> bf16 P
    softmax2048<<<Bq * Nq, 256>>>(Sp, Pb);

    // out = P @ Vt^T * gamma + x
    dim3 gO(Dq / 128, Nq / 128, Bq);
    hgemm<2><<<gO, blk, SMEM>>>(Pb, Vt, Nq, Nq, Nq,
                                (long long)Nq * Nq, (long long)Dq * Nq,
                                (long long)Nq * Dq, Dq, x, gamma, out);
}

// round 8
// speedup vs baseline: 1.0296x; 1.0296x over previous
#include <cuda_runtime.h>
#include <cuda_bf16.h>
#include <cstdint>
#include <math.h>

#define Bq 4
#define Nq 2048
#define Dq 1024
#define MTOT (Bq * Nq)   // 8192

typedef __nv_bfloat16 bf16;

// ---------------- scratch (device globals; allocation-free) ----------------
__device__ __align__(16) bf16  g_xb [(size_t)MTOT * Dq];
__device__ __align__(16) bf16  g_Wqb[(size_t)Dq * Dq];
__device__ __align__(16) bf16  g_Wkb[(size_t)Dq * Dq];
__device__ __align__(16) bf16  g_Wvb[(size_t)Dq * Dq];
__device__ __align__(16) bf16  g_Qb [(size_t)MTOT * Dq];
__device__ __align__(16) bf16  g_Kb [(size_t)MTOT * Dq];
__device__ __align__(16) bf16  g_Vt [(size_t)Bq * Dq * Nq];   // [b][d][n]
__device__ __align__(16) bf16  g_Pb [(size_t)Bq * Nq * Nq];   // exp(scores), unnormalized
__device__ __align__(16) float g_part[(size_t)MTOT * 32];     // per-(row, coltile) partial sums
__device__ __align__(16) float g_rinv[(size_t)MTOT];          // 1 / rowsum

// ---------------- helpers ----------------
__device__ __forceinline__ uint32_t smem_u32(const void* p) {
    uint32_t a;
    asm("{ .reg .u64 t; cvta.to.shared.u64 t, %1; cvt.u32.u64 %0, t; }" : "=r"(a) : "l"(p));
    return a;
}
#define CP_ASYNC16(dst, src) asm volatile("cp.async.cg.shared.global [%0], [%1], 16;" :: "r"(dst), "l"(src))
#define CP_COMMIT()          asm volatile("cp.async.commit_group;" ::: "memory")
#define CP_WAIT1()           asm volatile("cp.async.wait_group 1;" ::: "memory")

#define LDSM4(r0, r1, r2, r3, addr)                                             \
    asm volatile("ldmatrix.sync.aligned.m8n8.x4.shared.b16 {%0,%1,%2,%3}, [%4];" \
        : "=r"(r0), "=r"(r1), "=r"(r2), "=r"(r3) : "r"(addr))

#define MMA16816(d, a, b0, b1)                                                  \
    asm volatile("mma.sync.aligned.m16n8k16.row.col.f32.bf16.bf16.f32 "         \
        "{%0,%1,%2,%3}, {%4,%5,%6,%7}, {%8,%9}, {%0,%1,%2,%3};"                 \
        : "+f"((d)[0]), "+f"((d)[1]), "+f"((d)[2]), "+f"((d)[3])                \
        : "r"((a)[0]), "r"((a)[1]), "r"((a)[2]), "r"((a)[3]), "r"(b0), "r"(b1))

// ---------------------------------------------------------------------------
// NT bf16 HMMA GEMM: C[m,n] = sum_k A[m,k]*B[n,k]. Tile 128x128, BK=64,
// 3-stage cp.async pipeline, 4 warps (2x2), warp tile 64x64, fp32 accum.
// EPI 0: +bias -> bf16 C
// EPI 3: +bias -> bf16 transposed (Vt)
// EPI 1: exp(acc/32) -> bf16 P, plus per-(row,tile) partial sums -> part
// EPI 2: acc * (gamma * rinv[row]) + x -> fp32 out
// ---------------------------------------------------------------------------
#define BKq 64
#define STAGE_BYTES 32768u   // A tile 16KB + B tile 16KB

template <int EPI>
__global__ __launch_bounds__(128, 2)
void hgemm(const bf16* __restrict__ A, const bf16* __restrict__ Bm,
           int lda, int ldb, int K, long long sA, long long sB, long long sC,
           int ldc, const float* __restrict__ ep0, const float* __restrict__ ep1,
           float* __restrict__ part, const float* __restrict__ rinv,
           void* __restrict__ Cout)
{
    extern __shared__ char smem[];
    const int tid  = threadIdx.x;
    const int wid  = tid >> 5;
    const int lane = tid & 31;
    const int wm   = wid & 1;    // 2 warps along M (64 rows each)
    const int wn   = wid >> 1;   // 2 warps along N (64 cols each)
    const int z    = blockIdx.z;
    const int rowBase = blockIdx.y * 128;
    const int colBase = blockIdx.x * 128;

    const bf16* Ab = A + (long long)z * sA;
    const bf16* Bb = Bm + (long long)z * sB;
    const uint32_t sbase = smem_u32(smem);

    const int niter = K / BKq;

#define ISSUE_STAGE(c, s) do {                                                  \
        uint32_t aOff = sbase + (uint32_t)(s) * STAGE_BYTES;                    \
        uint32_t bOff = aOff + 16384u;                                          \
        _Pragma("unroll")                                                       \
        for (int i = 0; i < 8; i++) {                                           \
            int idx = tid + i * 128;                                            \
            int r = idx >> 3, ch = idx & 7;                                     \
            uint32_t sw = (uint32_t)((ch ^ (r & 7)) << 4) + (uint32_t)r * 128u; \
            CP_ASYNC16(aOff + sw, Ab + (size_t)(rowBase + r) * lda + (c) * BKq + ch * 8); \
            CP_ASYNC16(bOff + sw, Bb + (size_t)(colBase + r) * ldb + (c) * BKq + ch * 8); \
        }                                                                       \
        CP_COMMIT();                                                            \
    } while (0)

    float acc[4][8][4];
#pragma unroll
    for (int i = 0; i < 4; i++)
#pragma unroll
        for (int j = 0; j < 8; j++)
#pragma unroll
            for (int e = 0; e < 4; e++) acc[i][j][e] = 0.f;

    ISSUE_STAGE(0, 0);
    ISSUE_STAGE(1, 1);

    for (int c = 0; c < niter; c++) {
        CP_WAIT1();
        __syncthreads();
        if (c + 2 < niter) { ISSUE_STAGE(c + 2, (c + 2) % 3); }
        else               { CP_COMMIT(); }   // keep group count uniform

        uint32_t aBase = sbase + (uint32_t)(c % 3) * STAGE_BYTES;
        uint32_t bBase = aBase + 16384u;

#pragma unroll
        for (int kk = 0; kk < 4; kk++) {
            const int ch = kk * 2 + (lane >> 4);
            uint32_t af[4][4];
#pragma unroll
            for (int i = 0; i < 4; i++) {
                int r = wm * 64 + i * 16 + (lane & 15);
                uint32_t addr = aBase + (uint32_t)r * 128u + (uint32_t)((ch ^ (r & 7)) << 4);
                LDSM4(af[i][0], af[i][1], af[i][2], af[i][3], addr);
            }
            uint32_t bfr[4][4];
#pragma unroll
            for (int jj = 0; jj < 4; jj++) {
                int r = wn * 64 + jj * 16 + (lane & 15);
                uint32_t addr = bBase + (uint32_t)r * 128u + (uint32_t)((ch ^ (r & 7)) << 4);
                LDSM4(bfr[jj][0], bfr[jj][1], bfr[jj][2], bfr[jj][3], addr);
            }
#pragma unroll
            for (int i = 0; i < 4; i++)
#pragma unroll
                for (int j = 0; j < 8; j++)
                    MMA16816(acc[i][j], af[i], bfr[j >> 1][j & 1], bfr[j >> 1][(j & 1) + 2]);
        }
    }
#undef ISSUE_STAGE

    // ---------------- epilogue ----------------
    const float gma = (EPI == 2) ? ep1[0] : 0.f;

#pragma unroll
    for (int i = 0; i < 4; i++) {
        const int row0 = rowBase + wm * 64 + i * 16 + (lane >> 2);
        const int row1 = row0 + 8;

        if (EPI == 1) {
            // exp + bf16 store + row partial sums
            bf16* P = (bf16*)Cout + (long long)z * sC;
            float s0 = 0.f, s1 = 0.f;
#pragma unroll
            for (int j = 0; j < 8; j++) {
                const int col = colBase + wn * 64 + j * 8 + (lane & 3) * 2;
                float e0 = __expf(acc[i][j][0] * 0.03125f);
                float e1 = __expf(acc[i][j][1] * 0.03125f);
                float e2 = __expf(acc[i][j][2] * 0.03125f);
                float e3 = __expf(acc[i][j][3] * 0.03125f);
                *(__nv_bfloat162*)(P + (size_t)row0 * ldc + col) = __floats2bfloat162_rn(e0, e1);
                *(__nv_bfloat162*)(P + (size_t)row1 * ldc + col) = __floats2bfloat162_rn(e2, e3);
                s0 += e0 + e1;
                s1 += e2 + e3;
            }
            s0 += __shfl_xor_sync(0xFFFFFFFFu, s0, 1);
            s0 += __shfl_xor_sync(0xFFFFFFFFu, s0, 2);
            s1 += __shfl_xor_sync(0xFFFFFFFFu, s1, 1);
            s1 += __shfl_xor_sync(0xFFFFFFFFu, s1, 2);
            if ((lane & 3) == 0) {
                const int slot = blockIdx.x * 2 + wn;
                part[(((size_t)z * Nq + row0) << 5) + slot] = s0;
                part[(((size_t)z * Nq + row1) << 5) + slot] = s1;
            }
        } else if (EPI == 2) {
            float* O = (float*)Cout + (long long)z * sC;
            const float* xp = ep0 + (long long)z * sC;
            const float f0 = gma * __ldg(&rinv[(size_t)z * Nq + row0]);
            const float f1 = gma * __ldg(&rinv[(size_t)z * Nq + row1]);
#pragma unroll
            for (int j = 0; j < 8; j++) {
                const int col = colBase + wn * 64 + j * 8 + (lane & 3) * 2;
                float2 x0 = *(const float2*)(xp + (size_t)row0 * ldc + col);
                float2 x1 = *(const float2*)(xp + (size_t)row1 * ldc + col);
                float2 v0 = make_float2(acc[i][j][0] * f0 + x0.x, acc[i][j][1] * f0 + x0.y);
                float2 v1 = make_float2(acc[i][j][2] * f1 + x1.x, acc[i][j][3] * f1 + x1.y);
                *(float2*)(O + (size_t)row0 * ldc + col) = v0;
                *(float2*)(O + (size_t)row1 * ldc + col) = v1;
            }
        } else {
#pragma unroll
            for (int j = 0; j < 8; j++) {
                const int col = colBase + wn * 64 + j * 8 + (lane & 3) * 2;
                const float a0 = acc[i][j][0], a1 = acc[i][j][1];
                const float a2 = acc[i][j][2], a3 = acc[i][j][3];
                if (EPI == 0) {
                    bf16* C = (bf16*)Cout;
                    float b0 = ep0[col], b1 = ep0[col + 1];
                    __nv_bfloat162 h0 = __floats2bfloat162_rn(a0 + b0, a1 + b1);
                    __nv_bfloat162 h1 = __floats2bfloat162_rn(a2 + b0, a3 + b1);
                    *(__nv_bfloat162*)(C + (size_t)row0 * ldc + col) = h0;
                    *(__nv_bfloat162*)(C + (size_t)row1 * ldc + col) = h1;
                } else {  // EPI 3: transposed V store
                    bf16* Vt = (bf16*)Cout;
                    float b0 = ep0[col], b1 = ep0[col + 1];
                    int bz  = row0 >> 11;
                    int mm0 = row0 & 2047, mm1 = row1 & 2047;
                    size_t base0 = ((size_t)(bz << 10) + col) * Nq;
                    size_t base1 = ((size_t)(bz << 10) + col + 1) * Nq;
                    Vt[base0 + mm0] = __float2bfloat16(a0 + b0);
                    Vt[base1 + mm0] = __float2bfloat16(a1 + b1);
                    Vt[base0 + mm1] = __float2bfloat16(a2 + b0);
                    Vt[base1 + mm1] = __float2bfloat16(a3 + b1);
                }
            }
        }
    }
}

// ---------------------------------------------------------------------------
__global__ __launch_bounds__(256)
void cvt_f32_bf16(const float* __restrict__ in, bf16* __restrict__ out, int n4)
{
    int i = blockIdx.x * blockDim.x + threadIdx.x;
    if (i < n4) {
        float4 v = reinterpret_cast<const float4*>(in)[i];
        __nv_bfloat162 a = __floats2bfloat162_rn(v.x, v.y);
        __nv_bfloat162 b = __floats2bfloat162_rn(v.z, v.w);
        uint2 u;
        u.x = *(uint32_t*)&a;
        u.y = *(uint32_t*)&b;
        reinterpret_cast<uint2*>(out)[i] = u;
    }
}

// rowsum over 32 partials per row -> reciprocal
__global__ __launch_bounds__(256)
void rowsum_inv(const float* __restrict__ part, float* __restrict__ rinv)
{
    int r = blockIdx.x * blockDim.x + threadIdx.x;   // 0..MTOT-1
    float s = 0.f;
#pragma unroll
    for (int t = 0; t < 32; t += 4) {
        float4 v = *reinterpret_cast<const float4*>(part + ((size_t)r << 5) + t);
        s += v.x + v.y + v.z + v.w;
    }
    rinv[r] = 1.f / s;
}

// ---------------------------------------------------------------------------
extern "C" void kernel_launch(void* const* d_in, const int* in_sizes, int n_in,
                              void* d_out, int out_size)
{
    const float* x     = (const float*)d_in[0];
    const float* Wq    = (const float*)d_in[1];
    const float* bqv   = (const float*)d_in[2];
    const float* Wk    = (const float*)d_in[3];
    const float* bkv   = (const float*)d_in[4];
    const float* Wv    = (const float*)d_in[5];
    const float* bvv   = (const float*)d_in[6];
    const float* gamma = (const float*)d_in[7];
    float* out = (float*)d_out;

    bf16 *xb, *Wqb, *Wkb, *Wvb, *Qb, *Kb, *Vt, *Pb;
    float *part, *rinv;
    cudaGetSymbolAddress((void**)&xb,   g_xb);
    cudaGetSymbolAddress((void**)&Wqb,  g_Wqb);
    cudaGetSymbolAddress((void**)&Wkb,  g_Wkb);
    cudaGetSymbolAddress((void**)&Wvb,  g_Wvb);
    cudaGetSymbolAddress((void**)&Qb,   g_Qb);
    cudaGetSymbolAddress((void**)&Kb,   g_Kb);
    cudaGetSymbolAddress((void**)&Vt,   g_Vt);
    cudaGetSymbolAddress((void**)&Pb,   g_Pb);
    cudaGetSymbolAddress((void**)&part, g_part);
    cudaGetSymbolAddress((void**)&rinv, g_rinv);

    const int SMEM = 96 * 1024;
    cudaFuncSetAttribute(hgemm<0>, cudaFuncAttributeMaxDynamicSharedMemorySize, SMEM);
    cudaFuncSetAttribute(hgemm<1>, cudaFuncAttributeMaxDynamicSharedMemorySize, SMEM);
    cudaFuncSetAttribute(hgemm<2>, cudaFuncAttributeMaxDynamicSharedMemorySize, SMEM);
    cudaFuncSetAttribute(hgemm<3>, cudaFuncAttributeMaxDynamicSharedMemorySize, SMEM);

    // fp32 -> bf16 conversions
    cvt_f32_bf16<<<(MTOT * Dq / 4 + 255) / 256, 256>>>(x, xb, MTOT * Dq / 4);
    cvt_f32_bf16<<<(Dq * Dq / 4 + 255) / 256, 256>>>(Wq, Wqb, Dq * Dq / 4);
    cvt_f32_bf16<<<(Dq * Dq / 4 + 255) / 256, 256>>>(Wk, Wkb, Dq * Dq / 4);
    cvt_f32_bf16<<<(Dq * Dq / 4 + 255) / 256, 256>>>(Wv, Wvb, Dq * Dq / 4);

    dim3 blk(128);

    // projections: M=8192, N=1024, K=1024
    dim3 gP(Dq / 128, MTOT / 128, 1);
    hgemm<0><<<gP, blk, SMEM>>>(xb, Wqb, Dq, Dq, Dq, 0, 0, 0, Dq, bqv, nullptr, nullptr, nullptr, Qb);
    hgemm<0><<<gP, blk, SMEM>>>(xb, Wkb, Dq, Dq, Dq, 0, 0, 0, Dq, bkv, nullptr, nullptr, nullptr, Kb);
    hgemm<3><<<gP, blk, SMEM>>>(xb, Wvb, Dq, Dq, Dq, 0, 0, 0, Dq, bvv, nullptr, nullptr, nullptr, Vt);

    // P = exp(Q K^T / 32) (bf16) + row partial sums, per batch
    dim3 gS(Nq / 128, Nq / 128, Bq);
    hgemm<1><<<gS, blk, SMEM>>>(Qb, Kb, Dq, Dq, Dq,
                                (long long)Nq * Dq, (long long)Nq * Dq,
                                (long long)Nq * Nq, Nq, nullptr, nullptr, part, nullptr, Pb);

    // rinv = 1 / rowsum
    rowsum_inv<<<MTOT / 256, 256>>>(part, rinv);

    // out = (P @ Vt^T) * gamma * rinv + x
    dim3 gO(Dq / 128, Nq / 128, Bq);
    hgemm<2><<<gO, blk, SMEM>>>(Pb, Vt, Nq, Nq, Nq,
                                (long long)Nq * Nq, (long long)Dq * Nq,
                                (long long)Nq * Dq, Dq, x, gamma, nullptr, rinv, out);
}